// round 1
// baseline (speedup 1.0000x reference)
#include <cuda_runtime.h>
#include <cstdint>

// Problem constants (fixed for this problem instance)
#define DD 128            // feature dim
#define MAXROWS (2*50000) // B*N

// Scratch (allocation-free rule: __device__ globals)
__device__ float g_m[MAXROWS * DD];    // m = h @ W_msg^T   (51.2 MB)
__device__ float g_agg[MAXROWS * DD];  // scatter target    (51.2 MB)

// ---------------------------------------------------------------------------
// helpers
// ---------------------------------------------------------------------------
__device__ __forceinline__ void red_add_f32x4(float* p, float4 v) {
    asm volatile("red.global.add.v4.f32 [%0], {%1,%2,%3,%4};"
                 :: "l"(p), "f"(v.x), "f"(v.y), "f"(v.z), "f"(v.w)
                 : "memory");
}

// ---------------------------------------------------------------------------
// Kernel 1: m[row,:] = h[row,:] @ W_msg^T        (rows = B*N, K = 128)
// Tile: 64 rows x 128 outputs per block, 256 threads.
// Thread (tj = tid&15, tn = tid>>4): 8 outputs (tj*8..), 4 rows (tn*4..).
// ---------------------------------------------------------------------------
#define WT_STRIDE 132
#define CSA_STRIDE 132
#define SMEM_A ((128*WT_STRIDE + 64*CSA_STRIDE) * 4)

__global__ __launch_bounds__(256) void msg_gemm(
    const float* __restrict__ h, const float* __restrict__ Wmsg,
    float* __restrict__ m, int rows)
{
    extern __shared__ float sm[];
    float* Wt = sm;                       // [128][132]  Wt[k][j] = W[j][k]
    float* cs = sm + 128 * WT_STRIDE;     // [64][132]
    const int tid = threadIdx.x;
    const int row0 = blockIdx.x * 64;

    for (int idx = tid; idx < 128 * 128; idx += 256) {
        int j = idx >> 7, k = idx & 127;
        Wt[k * WT_STRIDE + j] = Wmsg[idx];
    }
    for (int idx = tid; idx < 64 * 128; idx += 256) {
        int rr = idx >> 7, k = idx & 127;
        int gr = row0 + rr;
        cs[rr * CSA_STRIDE + k] = (gr < rows) ? h[gr * DD + k] : 0.f;
    }
    __syncthreads();

    const int tj = tid & 15, tn = tid >> 4;
    const int j0 = tj << 3;

    float acc[4][8];
    #pragma unroll
    for (int t = 0; t < 4; ++t)
        #pragma unroll
        for (int u = 0; u < 8; ++u) acc[t][u] = 0.f;

    #pragma unroll 4
    for (int k = 0; k < 128; ++k) {
        const float4 w0 = *reinterpret_cast<const float4*>(&Wt[k * WT_STRIDE + j0]);
        const float4 w1 = *reinterpret_cast<const float4*>(&Wt[k * WT_STRIDE + j0 + 4]);
        #pragma unroll
        for (int t = 0; t < 4; ++t) {
            const float c = cs[(tn * 4 + t) * CSA_STRIDE + k];
            acc[t][0] = fmaf(c, w0.x, acc[t][0]);
            acc[t][1] = fmaf(c, w0.y, acc[t][1]);
            acc[t][2] = fmaf(c, w0.z, acc[t][2]);
            acc[t][3] = fmaf(c, w0.w, acc[t][3]);
            acc[t][4] = fmaf(c, w1.x, acc[t][4]);
            acc[t][5] = fmaf(c, w1.y, acc[t][5]);
            acc[t][6] = fmaf(c, w1.z, acc[t][6]);
            acc[t][7] = fmaf(c, w1.w, acc[t][7]);
        }
    }

    #pragma unroll
    for (int t = 0; t < 4; ++t) {
        int gr = row0 + tn * 4 + t;
        if (gr < rows) {
            float4 o0 = make_float4(acc[t][0], acc[t][1], acc[t][2], acc[t][3]);
            float4 o1 = make_float4(acc[t][4], acc[t][5], acc[t][6], acc[t][7]);
            *reinterpret_cast<float4*>(&m[gr * DD + j0])     = o0;
            *reinterpret_cast<float4*>(&m[gr * DD + j0 + 4]) = o1;
        }
    }
}

// ---------------------------------------------------------------------------
// Kernel 2: scatter.  One warp per edge, both batches.
// agg[b, tgt] += m[b, src] * rel_emb[rel]
// ---------------------------------------------------------------------------
__global__ __launch_bounds__(256) void scatter_edges(
    const float* __restrict__ m, const float* __restrict__ rel_emb,
    const int* __restrict__ esrc, const int* __restrict__ etgt,
    const int* __restrict__ erel, float* __restrict__ agg,
    int E, int ND)
{
    const int e = (blockIdx.x * blockDim.x + threadIdx.x) >> 5;
    if (e >= E) return;
    const int lane = threadIdx.x & 31;

    const int s = __ldg(&esrc[e]);
    const int t = __ldg(&etgt[e]);
    const int r = __ldg(&erel[e]);

    const float4 rv = *reinterpret_cast<const float4*>(&rel_emb[r * DD + lane * 4]);
    const float4 a0 = *reinterpret_cast<const float4*>(&m[s * DD + lane * 4]);
    const float4 a1 = *reinterpret_cast<const float4*>(&m[ND + s * DD + lane * 4]);

    float4 v0 = make_float4(a0.x * rv.x, a0.y * rv.y, a0.z * rv.z, a0.w * rv.w);
    float4 v1 = make_float4(a1.x * rv.x, a1.y * rv.y, a1.z * rv.z, a1.w * rv.w);

    red_add_f32x4(&agg[t * DD + lane * 4], v0);
    red_add_f32x4(&agg[ND + t * DD + lane * 4], v1);
}

// ---------------------------------------------------------------------------
// Kernel 3: upd = relu(cat @ W_upd^T + b); out = LN(h + upd)*scale + bias
// Tile 64 rows x 128 outputs, K = 256. Same thread mapping as kernel 1.
// LN reduction across the 16 lanes (tj) that own one row (contiguous lanes
// since tid = tn*16 + tj -> shfl_xor 8/4/2/1 stays inside the 16-lane group).
// ---------------------------------------------------------------------------
#define CSC_STRIDE 260
#define SMEM_C ((256*WT_STRIDE + 64*CSC_STRIDE) * 4)

__global__ __launch_bounds__(256) void update_ln(
    const float* __restrict__ h, const float* __restrict__ agg,
    const float* __restrict__ Wupd, const float* __restrict__ bupd,
    const float* __restrict__ lns, const float* __restrict__ lnb,
    float* __restrict__ out, int rows)
{
    extern __shared__ float sm[];
    float* Wt = sm;                       // [256][132]  Wt[k][j] = W[j][k]
    float* cs = sm + 256 * WT_STRIDE;     // [64][260]   cat = [h | agg]
    const int tid = threadIdx.x;
    const int row0 = blockIdx.x * 64;

    for (int idx = tid; idx < 128 * 256; idx += 256) {
        int j = idx >> 8, k = idx & 255;
        Wt[k * WT_STRIDE + j] = Wupd[idx];
    }
    for (int idx = tid; idx < 64 * 256; idx += 256) {
        int rr = idx >> 8, k = idx & 255;
        int gr = row0 + rr;
        float v = 0.f;
        if (gr < rows)
            v = (k < 128) ? h[gr * DD + k] : agg[gr * DD + (k - 128)];
        cs[rr * CSC_STRIDE + k] = v;
    }
    __syncthreads();

    const int tj = tid & 15, tn = tid >> 4;
    const int j0 = tj << 3;

    float acc[4][8];
    #pragma unroll
    for (int t = 0; t < 4; ++t)
        #pragma unroll
        for (int u = 0; u < 8; ++u) acc[t][u] = 0.f;

    #pragma unroll 4
    for (int k = 0; k < 256; ++k) {
        const float4 w0 = *reinterpret_cast<const float4*>(&Wt[k * WT_STRIDE + j0]);
        const float4 w1 = *reinterpret_cast<const float4*>(&Wt[k * WT_STRIDE + j0 + 4]);
        #pragma unroll
        for (int t = 0; t < 4; ++t) {
            const float c = cs[(tn * 4 + t) * CSC_STRIDE + k];
            acc[t][0] = fmaf(c, w0.x, acc[t][0]);
            acc[t][1] = fmaf(c, w0.y, acc[t][1]);
            acc[t][2] = fmaf(c, w0.z, acc[t][2]);
            acc[t][3] = fmaf(c, w0.w, acc[t][3]);
            acc[t][4] = fmaf(c, w1.x, acc[t][4]);
            acc[t][5] = fmaf(c, w1.y, acc[t][5]);
            acc[t][6] = fmaf(c, w1.z, acc[t][6]);
            acc[t][7] = fmaf(c, w1.w, acc[t][7]);
        }
    }

    // per-thread epilogue params for its 8 output columns
    float bu[8], sc[8], bi[8];
    #pragma unroll
    for (int u = 0; u < 8; ++u) {
        bu[u] = __ldg(&bupd[j0 + u]);
        sc[u] = __ldg(&lns[j0 + u]);
        bi[u] = __ldg(&lnb[j0 + u]);
    }

    #pragma unroll
    for (int t = 0; t < 4; ++t) {
        const int rl = tn * 4 + t;
        const int gr = row0 + rl;
        float y[8], s1 = 0.f, s2 = 0.f;
        #pragma unroll
        for (int u = 0; u < 8; ++u) {
            float v = acc[t][u] + bu[u];
            v = fmaxf(v, 0.f);
            v += cs[rl * CSC_STRIDE + j0 + u];   // residual: h value from cat tile
            y[u] = v;
            s1 += v;
            s2 += v * v;
        }
        // reduce over the 16 lanes owning this row
        #pragma unroll
        for (int off = 8; off >= 1; off >>= 1) {
            s1 += __shfl_xor_sync(0xffffffffu, s1, off);
            s2 += __shfl_xor_sync(0xffffffffu, s2, off);
        }
        const float mu  = s1 * (1.f / 128.f);
        const float var = s2 * (1.f / 128.f) - mu * mu;
        const float rs  = rsqrtf(var + 1e-5f);
        if (gr < rows) {
            float4 o0 = make_float4((y[0]-mu)*rs*sc[0]+bi[0], (y[1]-mu)*rs*sc[1]+bi[1],
                                    (y[2]-mu)*rs*sc[2]+bi[2], (y[3]-mu)*rs*sc[3]+bi[3]);
            float4 o1 = make_float4((y[4]-mu)*rs*sc[4]+bi[4], (y[5]-mu)*rs*sc[5]+bi[5],
                                    (y[6]-mu)*rs*sc[6]+bi[6], (y[7]-mu)*rs*sc[7]+bi[7]);
            *reinterpret_cast<float4*>(&out[gr * DD + j0])     = o0;
            *reinterpret_cast<float4*>(&out[gr * DD + j0 + 4]) = o1;
        }
    }
}

// ---------------------------------------------------------------------------
// host
// ---------------------------------------------------------------------------
extern "C" void kernel_launch(void* const* d_in, const int* in_sizes, int n_in,
                              void* d_out, int out_size)
{
    const float* h    = (const float*)d_in[0];
    const float* Wmsg = (const float*)d_in[1];
    const float* rel  = (const float*)d_in[2];
    const float* Wupd = (const float*)d_in[3];
    const float* bupd = (const float*)d_in[4];
    const float* lns  = (const float*)d_in[5];
    const float* lnb  = (const float*)d_in[6];
    const int*   esrc = (const int*)d_in[7];
    const int*   etgt = (const int*)d_in[8];
    const int*   erel = (const int*)d_in[9];
    float* out = (float*)d_out;

    const int E    = in_sizes[7];
    const int rows = in_sizes[0] / DD;     // B*N = 100000
    const int ND   = (rows / 2) * DD;      // per-batch stride

    void *pm = nullptr, *pa = nullptr;
    cudaGetSymbolAddress(&pm, g_m);
    cudaGetSymbolAddress(&pa, g_agg);
    float* d_m   = (float*)pm;
    float* d_agg = (float*)pa;

    cudaFuncSetAttribute(msg_gemm,  cudaFuncAttributeMaxDynamicSharedMemorySize, SMEM_A);
    cudaFuncSetAttribute(update_ln, cudaFuncAttributeMaxDynamicSharedMemorySize, SMEM_C);

    cudaMemsetAsync(d_agg, 0, (size_t)rows * DD * sizeof(float), 0);

    msg_gemm<<<(rows + 63) / 64, 256, SMEM_A>>>(h, Wmsg, d_m, rows);

    scatter_edges<<<(E + 7) / 8, 256>>>(d_m, rel, esrc, etgt, erel, d_agg, E, ND);

    update_ln<<<(rows + 63) / 64, 256, SMEM_C>>>(h, d_agg, Wupd, bupd, lns, lnb, out, rows);
}

// round 2
// speedup vs baseline: 2.3123x; 2.3123x over previous
#include <cuda_runtime.h>
#include <cstdint>

#define DD 128
#define MAXROWS (2*50000)
#define MAXN 50001
#define MAXE 800000

// scratch (__device__ globals — allocation-free rule)
__device__ float g_m[MAXROWS * DD];     // m = h @ W_msg^T
__device__ float g_agg[MAXROWS * DD];   // gathered messages
__device__ int   g_cnt[MAXN];           // per-target histogram
__device__ int   g_base[MAXN];          // exclusive prefix / fill cursors
__device__ int   g_sorted[MAXE];        // packed (src | rel<<17) sorted by target

// ---------------------------------------------------------------------------
// Kernel A: histogram of edge targets
// ---------------------------------------------------------------------------
__global__ __launch_bounds__(256) void hist_k(const int* __restrict__ etgt,
                                              int* __restrict__ cnt, int E)
{
    int e = blockIdx.x * blockDim.x + threadIdx.x;
    if (e < E) atomicAdd(&cnt[etgt[e]], 1);
}

// ---------------------------------------------------------------------------
// Kernel B: single-block exclusive scan of cnt[0..n) -> base[0..n)
// ---------------------------------------------------------------------------
__global__ __launch_bounds__(1024) void exscan_k(const int* __restrict__ cnt,
                                                 int* __restrict__ base, int n)
{
    __shared__ int ws[32];
    __shared__ int carry_s;
    const int tid = threadIdx.x;
    const int lane = tid & 31, wid = tid >> 5;
    if (tid == 0) carry_s = 0;
    __syncthreads();

    for (int chunk = 0; chunk < n; chunk += 1024) {
        const int i = chunk + tid;
        const int x = (i < n) ? cnt[i] : 0;
        int v = x;
        #pragma unroll
        for (int o = 1; o < 32; o <<= 1) {
            int t = __shfl_up_sync(0xffffffffu, v, o);
            if (lane >= o) v += t;
        }
        if (lane == 31) ws[wid] = v;
        __syncthreads();
        if (wid == 0) {
            int w = ws[lane];
            #pragma unroll
            for (int o = 1; o < 32; o <<= 1) {
                int t = __shfl_up_sync(0xffffffffu, w, o);
                if (lane >= o) w += t;
            }
            ws[lane] = w;
        }
        __syncthreads();
        const int woff = (wid > 0) ? ws[wid - 1] : 0;
        const int carry = carry_s;
        const int incl = v + woff + carry;
        if (i < n) base[i] = incl - x;
        __syncthreads();
        if (tid == 1023) carry_s = incl;
        __syncthreads();
    }
}

// ---------------------------------------------------------------------------
// Kernel C: fill sorted edge list (counting-sort scatter phase)
// After this, base[t] = original_base[t+1]; gather uses [base[t-1], base[t]).
// ---------------------------------------------------------------------------
__global__ __launch_bounds__(256) void fill_k(
    const int* __restrict__ esrc, const int* __restrict__ etgt,
    const int* __restrict__ erel, int* __restrict__ base,
    int* __restrict__ sorted, int E)
{
    int e = blockIdx.x * blockDim.x + threadIdx.x;
    if (e >= E) return;
    const int t = etgt[e];
    const int pos = atomicAdd(&base[t], 1);
    sorted[pos] = esrc[e] | (erel[e] << 17);
}

// ---------------------------------------------------------------------------
// Kernel 1: m[row,:] = h[row,:] @ W_msg^T     (rows = B*N)
// 256 threads, tile 64 rows x 128 cols. warp -> 16 cols (broadcast W loads),
// lane -> rows {lane, lane+32}. acc[2][16] per thread.
// ---------------------------------------------------------------------------
#define CS_STR 132
#define SMEM_G ((128*128 + 64*CS_STR) * 4)

__global__ __launch_bounds__(256) void msg_gemm(
    const float* __restrict__ h, const float* __restrict__ W,
    float* __restrict__ m, int rows)
{
    extern __shared__ float sm[];
    float* Wsm = sm;                   // [j*128 + k]  (row-major copy)
    float* cs  = sm + 128 * 128;       // [r*132 + k]
    const int tid = threadIdx.x;
    const int row0 = blockIdx.x * 64;

    const float4* W4 = (const float4*)W;
    float4* Wsm4 = (float4*)Wsm;
    #pragma unroll 4
    for (int i = tid; i < 4096; i += 256) Wsm4[i] = W4[i];

    const float4* h4 = (const float4*)h;
    #pragma unroll 2
    for (int i = tid; i < 2048; i += 256) {
        int rr = i >> 5, k4 = i & 31;
        int gr = row0 + rr;
        float4 v = (gr < rows) ? h4[gr * 32 + k4] : make_float4(0.f,0.f,0.f,0.f);
        *(float4*)&cs[rr * CS_STR + k4 * 4] = v;
    }
    __syncthreads();

    const int lane = tid & 31, warp = tid >> 5;
    const int j0 = warp * 16;
    const float* cs0 = &cs[lane * CS_STR];
    const float* cs1 = &cs[(lane + 32) * CS_STR];

    float acc[2][16];
    #pragma unroll
    for (int t = 0; t < 2; ++t)
        #pragma unroll
        for (int jj = 0; jj < 16; ++jj) acc[t][jj] = 0.f;

    #pragma unroll 4
    for (int k4 = 0; k4 < 32; ++k4) {
        const float4 c0 = *(const float4*)&cs0[k4 * 4];
        const float4 c1 = *(const float4*)&cs1[k4 * 4];
        #pragma unroll
        for (int jj = 0; jj < 16; ++jj) {
            const float4 w = *(const float4*)&Wsm[(j0 + jj) * 128 + k4 * 4];
            acc[0][jj] = fmaf(c0.x, w.x, acc[0][jj]);
            acc[0][jj] = fmaf(c0.y, w.y, acc[0][jj]);
            acc[0][jj] = fmaf(c0.z, w.z, acc[0][jj]);
            acc[0][jj] = fmaf(c0.w, w.w, acc[0][jj]);
            acc[1][jj] = fmaf(c1.x, w.x, acc[1][jj]);
            acc[1][jj] = fmaf(c1.y, w.y, acc[1][jj]);
            acc[1][jj] = fmaf(c1.z, w.z, acc[1][jj]);
            acc[1][jj] = fmaf(c1.w, w.w, acc[1][jj]);
        }
    }

    #pragma unroll
    for (int t = 0; t < 2; ++t) {
        const int gr = row0 + lane + t * 32;
        if (gr < rows) {
            #pragma unroll
            for (int q = 0; q < 4; ++q) {
                float4 o = make_float4(acc[t][4*q], acc[t][4*q+1],
                                       acc[t][4*q+2], acc[t][4*q+3]);
                *(float4*)&m[gr * DD + j0 + 4*q] = o;
            }
        }
    }
}

// ---------------------------------------------------------------------------
// Kernel 2: CSR gather. One warp per target node, both batches, no atomics.
// ---------------------------------------------------------------------------
__global__ __launch_bounds__(256) void gather_csr(
    const float* __restrict__ m, const float* __restrict__ rel_emb,
    const int* __restrict__ base, const int* __restrict__ sorted,
    float* __restrict__ agg, int N, int ND)
{
    const int nid = blockIdx.x * 8 + (threadIdx.x >> 5);
    if (nid >= N) return;
    const int lane = threadIdx.x & 31;

    const int start = (nid == 0) ? 0 : __ldg(&base[nid - 1]);
    const int end = __ldg(&base[nid]);

    const float4* m4 = (const float4*)m;
    const float4* r4 = (const float4*)rel_emb;
    const int ND4 = ND / 4;

    float4 a0 = make_float4(0.f,0.f,0.f,0.f);
    float4 a1 = make_float4(0.f,0.f,0.f,0.f);

    int i = start;
    for (; i + 1 < end; i += 2) {
        const int pA = __ldg(&sorted[i]);
        const int pB = __ldg(&sorted[i + 1]);
        const int sA = pA & 0x1FFFF, rA = pA >> 17;
        const int sB = pB & 0x1FFFF, rB = pB >> 17;
        const float4 rvA = r4[rA * 32 + lane];
        const float4 m0A = m4[sA * 32 + lane];
        const float4 m1A = m4[ND4 + sA * 32 + lane];
        const float4 rvB = r4[rB * 32 + lane];
        const float4 m0B = m4[sB * 32 + lane];
        const float4 m1B = m4[ND4 + sB * 32 + lane];
        a0.x = fmaf(m0A.x, rvA.x, a0.x); a0.y = fmaf(m0A.y, rvA.y, a0.y);
        a0.z = fmaf(m0A.z, rvA.z, a0.z); a0.w = fmaf(m0A.w, rvA.w, a0.w);
        a1.x = fmaf(m1A.x, rvA.x, a1.x); a1.y = fmaf(m1A.y, rvA.y, a1.y);
        a1.z = fmaf(m1A.z, rvA.z, a1.z); a1.w = fmaf(m1A.w, rvA.w, a1.w);
        a0.x = fmaf(m0B.x, rvB.x, a0.x); a0.y = fmaf(m0B.y, rvB.y, a0.y);
        a0.z = fmaf(m0B.z, rvB.z, a0.z); a0.w = fmaf(m0B.w, rvB.w, a0.w);
        a1.x = fmaf(m1B.x, rvB.x, a1.x); a1.y = fmaf(m1B.y, rvB.y, a1.y);
        a1.z = fmaf(m1B.z, rvB.z, a1.z); a1.w = fmaf(m1B.w, rvB.w, a1.w);
    }
    if (i < end) {
        const int p = __ldg(&sorted[i]);
        const int s = p & 0x1FFFF, r = p >> 17;
        const float4 rv = r4[r * 32 + lane];
        const float4 m0 = m4[s * 32 + lane];
        const float4 m1 = m4[ND4 + s * 32 + lane];
        a0.x = fmaf(m0.x, rv.x, a0.x); a0.y = fmaf(m0.y, rv.y, a0.y);
        a0.z = fmaf(m0.z, rv.z, a0.z); a0.w = fmaf(m0.w, rv.w, a0.w);
        a1.x = fmaf(m1.x, rv.x, a1.x); a1.y = fmaf(m1.y, rv.y, a1.y);
        a1.z = fmaf(m1.z, rv.z, a1.z); a1.w = fmaf(m1.w, rv.w, a1.w);
    }

    float4* agg4 = (float4*)agg;
    agg4[nid * 32 + lane] = a0;
    agg4[ND4 + nid * 32 + lane] = a1;
}

// ---------------------------------------------------------------------------
// Kernel 3: upd = relu([h|agg] @ W_upd^T + b); out = LN(h + upd)*scale + bias
// Same mapping as kernel 1. K=256 processed in two 128-chunks:
//   phase 0: agg with W_upd[:,128:256];  phase 1: h with W_upd[:,0:128]
// so the residual reads h from the still-resident cs tile.
// ---------------------------------------------------------------------------
__global__ __launch_bounds__(256) void update_ln(
    const float* __restrict__ h, const float* __restrict__ agg,
    const float* __restrict__ Wupd, const float* __restrict__ bupd,
    const float* __restrict__ lns, const float* __restrict__ lnb,
    float* __restrict__ out, int rows)
{
    extern __shared__ float sm[];
    float* Wsm = sm;                   // [j*128 + k-chunk]
    float* cs  = sm + 128 * 128;       // [r*132 + k]
    const int tid = threadIdx.x;
    const int row0 = blockIdx.x * 64;
    const int lane = tid & 31, warp = tid >> 5;
    const int j0 = warp * 16;

    float acc[2][16];
    #pragma unroll
    for (int t = 0; t < 2; ++t)
        #pragma unroll
        for (int jj = 0; jj < 16; ++jj) acc[t][jj] = 0.f;

    const float4* Wu4 = (const float4*)Wupd;
    float4* Wsm4 = (float4*)Wsm;

    #pragma unroll
    for (int ph = 0; ph < 2; ++ph) {
        const int off4 = ph ? 0 : 32;                       // ph0: cols 128..255
        const float4* src4 = (const float4*)(ph ? h : agg);

        #pragma unroll 4
        for (int i = tid; i < 4096; i += 256) {
            int j = i >> 5, k4 = i & 31;
            Wsm4[i] = Wu4[j * 64 + off4 + k4];
        }
        #pragma unroll 2
        for (int i = tid; i < 2048; i += 256) {
            int rr = i >> 5, k4 = i & 31;
            int gr = row0 + rr;
            float4 v = (gr < rows) ? src4[gr * 32 + k4] : make_float4(0.f,0.f,0.f,0.f);
            *(float4*)&cs[rr * CS_STR + k4 * 4] = v;
        }
        __syncthreads();

        const float* cs0 = &cs[lane * CS_STR];
        const float* cs1 = &cs[(lane + 32) * CS_STR];
        #pragma unroll 4
        for (int k4 = 0; k4 < 32; ++k4) {
            const float4 c0 = *(const float4*)&cs0[k4 * 4];
            const float4 c1 = *(const float4*)&cs1[k4 * 4];
            #pragma unroll
            for (int jj = 0; jj < 16; ++jj) {
                const float4 w = *(const float4*)&Wsm[(j0 + jj) * 128 + k4 * 4];
                acc[0][jj] = fmaf(c0.x, w.x, acc[0][jj]);
                acc[0][jj] = fmaf(c0.y, w.y, acc[0][jj]);
                acc[0][jj] = fmaf(c0.z, w.z, acc[0][jj]);
                acc[0][jj] = fmaf(c0.w, w.w, acc[0][jj]);
                acc[1][jj] = fmaf(c1.x, w.x, acc[1][jj]);
                acc[1][jj] = fmaf(c1.y, w.y, acc[1][jj]);
                acc[1][jj] = fmaf(c1.z, w.z, acc[1][jj]);
                acc[1][jj] = fmaf(c1.w, w.w, acc[1][jj]);
            }
        }
        __syncthreads();   // before Wsm/cs reuse (ph0->ph1) or red buffer (after ph1)
    }

    // epilogue: bias + relu + residual(h from cs) + LayerNorm
    float2* red2 = (float2*)Wsm;       // [row][warp] partial (s1, s2)

    #pragma unroll
    for (int t = 0; t < 2; ++t) {
        const int rl = lane + t * 32;
        float s1 = 0.f, s2 = 0.f;
        #pragma unroll
        for (int jj = 0; jj < 16; ++jj) {
            float v = fmaxf(acc[t][jj] + __ldg(&bupd[j0 + jj]), 0.f);
            v += cs[rl * CS_STR + j0 + jj];
            acc[t][jj] = v;
            s1 += v;
            s2 += v * v;
        }
        red2[rl * 8 + warp] = make_float2(s1, s2);
    }
    __syncthreads();

    #pragma unroll
    for (int t = 0; t < 2; ++t) {
        const int rl = lane + t * 32;
        const int gr = row0 + rl;
        float S1 = 0.f, S2 = 0.f;
        #pragma unroll
        for (int w = 0; w < 8; ++w) {
            float2 p = red2[rl * 8 + w];
            S1 += p.x; S2 += p.y;
        }
        const float mu  = S1 * (1.f / 128.f);
        const float var = S2 * (1.f / 128.f) - mu * mu;
        const float rs  = rsqrtf(var + 1e-5f);
        if (gr < rows) {
            #pragma unroll
            for (int q = 0; q < 4; ++q) {
                float4 o;
                o.x = (acc[t][4*q+0] - mu) * rs * __ldg(&lns[j0+4*q+0]) + __ldg(&lnb[j0+4*q+0]);
                o.y = (acc[t][4*q+1] - mu) * rs * __ldg(&lns[j0+4*q+1]) + __ldg(&lnb[j0+4*q+1]);
                o.z = (acc[t][4*q+2] - mu) * rs * __ldg(&lns[j0+4*q+2]) + __ldg(&lnb[j0+4*q+2]);
                o.w = (acc[t][4*q+3] - mu) * rs * __ldg(&lns[j0+4*q+3]) + __ldg(&lnb[j0+4*q+3]);
                *(float4*)&out[gr * DD + j0 + 4*q] = o;
            }
        }
    }
}

// ---------------------------------------------------------------------------
// host
// ---------------------------------------------------------------------------
extern "C" void kernel_launch(void* const* d_in, const int* in_sizes, int n_in,
                              void* d_out, int out_size)
{
    const float* h    = (const float*)d_in[0];
    const float* Wmsg = (const float*)d_in[1];
    const float* rel  = (const float*)d_in[2];
    const float* Wupd = (const float*)d_in[3];
    const float* bupd = (const float*)d_in[4];
    const float* lns  = (const float*)d_in[5];
    const float* lnb  = (const float*)d_in[6];
    const int*   esrc = (const int*)d_in[7];
    const int*   etgt = (const int*)d_in[8];
    const int*   erel = (const int*)d_in[9];
    float* out = (float*)d_out;

    const int E    = in_sizes[7];
    const int rows = in_sizes[0] / DD;     // B*N
    const int N    = rows / 2;
    const int ND   = N * DD;

    void *pm, *pa, *pc, *pb, *ps;
    cudaGetSymbolAddress(&pm, g_m);
    cudaGetSymbolAddress(&pa, g_agg);
    cudaGetSymbolAddress(&pc, g_cnt);
    cudaGetSymbolAddress(&pb, g_base);
    cudaGetSymbolAddress(&ps, g_sorted);
    float* d_m    = (float*)pm;
    float* d_agg  = (float*)pa;
    int*   d_cnt  = (int*)pc;
    int*   d_base = (int*)pb;
    int*   d_sort = (int*)ps;

    cudaFuncSetAttribute(msg_gemm,  cudaFuncAttributeMaxDynamicSharedMemorySize, SMEM_G);
    cudaFuncSetAttribute(update_ln, cudaFuncAttributeMaxDynamicSharedMemorySize, SMEM_G);

    // edge sort (counting sort by target)
    cudaMemsetAsync(d_cnt, 0, (size_t)N * sizeof(int), 0);
    hist_k<<<(E + 255) / 256, 256>>>(etgt, d_cnt, E);
    exscan_k<<<1, 1024>>>(d_cnt, d_base, N);
    fill_k<<<(E + 255) / 256, 256>>>(esrc, etgt, erel, d_base, d_sort, E);

    // m = h @ W_msg^T
    msg_gemm<<<(rows + 63) / 64, 256, SMEM_G>>>(h, Wmsg, d_m, rows);

    // agg[t] = sum_{e: tgt=t} m[src_e] * rel_emb[rel_e]
    gather_csr<<<(N + 7) / 8, 256>>>(d_m, rel, d_base, d_sort, d_agg, N, ND);

    // update + residual + layernorm
    update_ln<<<(rows + 63) / 64, 256, SMEM_G>>>(h, d_agg, Wupd, bupd, lns, lnb, out, rows);
}

// round 5
// speedup vs baseline: 3.1148x; 1.3471x over previous
#include <cuda_runtime.h>
#include <cstdint>

#define DD 128
#define MAXROWS (2*50000)
#define MAXN 50001
#define MAXE 800000

// scratch (__device__ globals — allocation-free rule)
__device__ float g_m[MAXROWS * DD];
__device__ float g_agg[MAXROWS * DD];
__device__ int   g_cnt[MAXN];
__device__ int   g_base[MAXN];
__device__ int   g_sorted[MAXE];

// ---------------------------------------------------------------------------
// helpers
// ---------------------------------------------------------------------------
// cvt.rna.tf32.f32 requires a .b32 destination (that was the R4 ptxas error)
__device__ __forceinline__ float to_tf32(float x) {
    uint32_t u;
    asm("cvt.rna.tf32.f32 %0, %1;" : "=r"(u) : "f"(x));
    return __uint_as_float(u);
}
__device__ __forceinline__ void split_tf32(float x, float& hi, float& lo) {
    hi = to_tf32(x);
    lo = to_tf32(x - hi);
}

__device__ __forceinline__ void mma_tf32(float* c, const float* a, const float* b) {
    asm volatile(
        "mma.sync.aligned.m16n8k8.row.col.f32.tf32.tf32.f32 "
        "{%0,%1,%2,%3}, {%4,%5,%6,%7}, {%8,%9}, {%0,%1,%2,%3};"
        : "+f"(c[0]), "+f"(c[1]), "+f"(c[2]), "+f"(c[3])
        : "r"(__float_as_uint(a[0])), "r"(__float_as_uint(a[1])),
          "r"(__float_as_uint(a[2])), "r"(__float_as_uint(a[3])),
          "r"(__float_as_uint(b[0])), "r"(__float_as_uint(b[1])));
}

// smem layout (floats), padded stride 36 (36g+q mod 32 hits all banks)
#define SA_STR 36
#define OF_ASH 0
#define OF_ASL (64 * SA_STR)
#define OF_BSH (2 * 64 * SA_STR)
#define OF_BSL (OF_BSH + 128 * SA_STR)
#define SM_FLOATS (OF_BSL + 128 * SA_STR)
#define SM_BYTES (SM_FLOATS * 4)       // 55296

// ============================================================================
// Edge sort (counting sort by target)
// ============================================================================
__global__ __launch_bounds__(256) void hist_k(const int* __restrict__ etgt,
                                              int* __restrict__ cnt, int E)
{
    int e = blockIdx.x * blockDim.x + threadIdx.x;
    if (e < E) atomicAdd(&cnt[etgt[e]], 1);
}

__global__ __launch_bounds__(1024) void exscan_k(const int* __restrict__ cnt,
                                                 int* __restrict__ base, int n)
{
    __shared__ int ws[32];
    __shared__ int carry_s;
    const int tid = threadIdx.x;
    const int lane = tid & 31, wid = tid >> 5;
    if (tid == 0) carry_s = 0;
    __syncthreads();

    for (int chunk = 0; chunk < n; chunk += 1024) {
        const int i = chunk + tid;
        const int x = (i < n) ? cnt[i] : 0;
        int v = x;
        #pragma unroll
        for (int o = 1; o < 32; o <<= 1) {
            int t = __shfl_up_sync(0xffffffffu, v, o);
            if (lane >= o) v += t;
        }
        if (lane == 31) ws[wid] = v;
        __syncthreads();
        if (wid == 0) {
            int w = ws[lane];
            #pragma unroll
            for (int o = 1; o < 32; o <<= 1) {
                int t = __shfl_up_sync(0xffffffffu, w, o);
                if (lane >= o) w += t;
            }
            ws[lane] = w;
        }
        __syncthreads();
        const int woff = (wid > 0) ? ws[wid - 1] : 0;
        const int carry = carry_s;
        const int incl = v + woff + carry;
        if (i < n) base[i] = incl - x;
        __syncthreads();
        if (tid == 1023) carry_s = incl;
        __syncthreads();
    }
}

__global__ __launch_bounds__(256) void fill_k(
    const int* __restrict__ esrc, const int* __restrict__ etgt,
    const int* __restrict__ erel, int* __restrict__ base,
    int* __restrict__ sorted, int E)
{
    int e = blockIdx.x * blockDim.x + threadIdx.x;
    if (e >= E) return;
    const int t = etgt[e];
    const int pos = atomicAdd(&base[t], 1);
    sorted[pos] = esrc[e] | (erel[e] << 17);
}

// ============================================================================
// Kernel 1: m = h @ W_msg^T  (mma.sync tf32x3)
// block: 64 rows x 128 cols, 8 warps (warp_m 0..1, warp_n 0..3), warp 32x32
// ============================================================================
__global__ __launch_bounds__(256) void msg_gemm_mma(
    const float* __restrict__ h, const float* __restrict__ W,
    float* __restrict__ m, int rows)
{
    extern __shared__ float sm[];
    float* Ash = sm + OF_ASH;
    float* Asl = sm + OF_ASL;
    float* Bsh = sm + OF_BSH;
    float* Bsl = sm + OF_BSL;

    const int tid = threadIdx.x;
    const int lane = tid & 31, wid = tid >> 5;
    const int g = lane >> 2, q = lane & 3;
    const int m0 = (wid >> 2) * 32, n0 = (wid & 3) * 32;
    const int row0 = blockIdx.x * 64;

    const float4* h4 = (const float4*)h;
    const float4* W4 = (const float4*)W;

    float c[2][4][4];
    #pragma unroll
    for (int mt = 0; mt < 2; ++mt)
        #pragma unroll
        for (int nt = 0; nt < 4; ++nt)
            #pragma unroll
            for (int k = 0; k < 4; ++k) c[mt][nt][k] = 0.f;

    for (int ch = 0; ch < 4; ++ch) {
        // stage A (64 x 32)
        #pragma unroll
        for (int i = tid; i < 512; i += 256) {
            const int r = i >> 3, j4 = i & 7;
            const int gr = row0 + r;
            float4 v = (gr < rows) ? h4[gr * 32 + ch * 8 + j4]
                                   : make_float4(0.f, 0.f, 0.f, 0.f);
            float4 hi, lo;
            split_tf32(v.x, hi.x, lo.x);
            split_tf32(v.y, hi.y, lo.y);
            split_tf32(v.z, hi.z, lo.z);
            split_tf32(v.w, hi.w, lo.w);
            *(float4*)&Ash[r * SA_STR + j4 * 4] = hi;
            *(float4*)&Asl[r * SA_STR + j4 * 4] = lo;
        }
        // stage B (128 x 32)
        #pragma unroll
        for (int i = tid; i < 1024; i += 256) {
            const int r = i >> 3, j4 = i & 7;
            float4 w = W4[r * 32 + ch * 8 + j4];
            float4 hi, lo;
            split_tf32(w.x, hi.x, lo.x);
            split_tf32(w.y, hi.y, lo.y);
            split_tf32(w.z, hi.z, lo.z);
            split_tf32(w.w, hi.w, lo.w);
            *(float4*)&Bsh[r * SA_STR + j4 * 4] = hi;
            *(float4*)&Bsl[r * SA_STR + j4 * 4] = lo;
        }
        __syncthreads();

        #pragma unroll
        for (int ks = 0; ks < 4; ++ks) {
            const int kc = ks * 8;
            float ah[2][4], al[2][4], bh[4][2], bl[4][2];
            #pragma unroll
            for (int mt = 0; mt < 2; ++mt) {
                const int rb = (m0 + mt * 16 + g) * SA_STR + kc + q;
                ah[mt][0] = Ash[rb];
                ah[mt][1] = Ash[rb + 8 * SA_STR];
                ah[mt][2] = Ash[rb + 4];
                ah[mt][3] = Ash[rb + 8 * SA_STR + 4];
                al[mt][0] = Asl[rb];
                al[mt][1] = Asl[rb + 8 * SA_STR];
                al[mt][2] = Asl[rb + 4];
                al[mt][3] = Asl[rb + 8 * SA_STR + 4];
            }
            #pragma unroll
            for (int nt = 0; nt < 4; ++nt) {
                const int rb = (n0 + nt * 8 + g) * SA_STR + kc + q;
                bh[nt][0] = Bsh[rb];
                bh[nt][1] = Bsh[rb + 4];
                bl[nt][0] = Bsl[rb];
                bl[nt][1] = Bsl[rb + 4];
            }
            #pragma unroll
            for (int mt = 0; mt < 2; ++mt)
                #pragma unroll
                for (int nt = 0; nt < 4; ++nt) {
                    mma_tf32(c[mt][nt], ah[mt], bh[nt]);
                    mma_tf32(c[mt][nt], ah[mt], bl[nt]);
                    mma_tf32(c[mt][nt], al[mt], bh[nt]);
                }
        }
        __syncthreads();
    }

    // epilogue
    #pragma unroll
    for (int mt = 0; mt < 2; ++mt) {
        const int rlo = row0 + m0 + mt * 16 + g;
        const int rhi = rlo + 8;
        #pragma unroll
        for (int nt = 0; nt < 4; ++nt) {
            const int col = n0 + nt * 8 + q * 2;
            if (rlo < rows)
                *(float2*)&m[rlo * DD + col] = make_float2(c[mt][nt][0], c[mt][nt][1]);
            if (rhi < rows)
                *(float2*)&m[rhi * DD + col] = make_float2(c[mt][nt][2], c[mt][nt][3]);
        }
    }
}

// ============================================================================
// Kernel 2: CSR gather. One warp per target node, both batches, no atomics.
// ============================================================================
__global__ __launch_bounds__(256) void gather_csr(
    const float* __restrict__ m, const float* __restrict__ rel_emb,
    const int* __restrict__ base, const int* __restrict__ sorted,
    float* __restrict__ agg, int N, int ND)
{
    const int nid = blockIdx.x * 8 + (threadIdx.x >> 5);
    if (nid >= N) return;
    const int lane = threadIdx.x & 31;

    const int start = (nid == 0) ? 0 : __ldg(&base[nid - 1]);
    const int end = __ldg(&base[nid]);

    const float4* m4 = (const float4*)m;
    const float4* r4 = (const float4*)rel_emb;
    const int ND4 = ND / 4;

    float4 a0 = make_float4(0.f,0.f,0.f,0.f);
    float4 a1 = make_float4(0.f,0.f,0.f,0.f);

    int i = start;
    for (; i + 1 < end; i += 2) {
        const int pA = __ldg(&sorted[i]);
        const int pB = __ldg(&sorted[i + 1]);
        const int sA = pA & 0x1FFFF, rA = pA >> 17;
        const int sB = pB & 0x1FFFF, rB = pB >> 17;
        const float4 rvA = r4[rA * 32 + lane];
        const float4 m0A = m4[sA * 32 + lane];
        const float4 m1A = m4[ND4 + sA * 32 + lane];
        const float4 rvB = r4[rB * 32 + lane];
        const float4 m0B = m4[sB * 32 + lane];
        const float4 m1B = m4[ND4 + sB * 32 + lane];
        a0.x = fmaf(m0A.x, rvA.x, a0.x); a0.y = fmaf(m0A.y, rvA.y, a0.y);
        a0.z = fmaf(m0A.z, rvA.z, a0.z); a0.w = fmaf(m0A.w, rvA.w, a0.w);
        a1.x = fmaf(m1A.x, rvA.x, a1.x); a1.y = fmaf(m1A.y, rvA.y, a1.y);
        a1.z = fmaf(m1A.z, rvA.z, a1.z); a1.w = fmaf(m1A.w, rvA.w, a1.w);
        a0.x = fmaf(m0B.x, rvB.x, a0.x); a0.y = fmaf(m0B.y, rvB.y, a0.y);
        a0.z = fmaf(m0B.z, rvB.z, a0.z); a0.w = fmaf(m0B.w, rvB.w, a0.w);
        a1.x = fmaf(m1B.x, rvB.x, a1.x); a1.y = fmaf(m1B.y, rvB.y, a1.y);
        a1.z = fmaf(m1B.z, rvB.z, a1.z); a1.w = fmaf(m1B.w, rvB.w, a1.w);
    }
    if (i < end) {
        const int p = __ldg(&sorted[i]);
        const int s = p & 0x1FFFF, r = p >> 17;
        const float4 rv = r4[r * 32 + lane];
        const float4 m0 = m4[s * 32 + lane];
        const float4 m1 = m4[ND4 + s * 32 + lane];
        a0.x = fmaf(m0.x, rv.x, a0.x); a0.y = fmaf(m0.y, rv.y, a0.y);
        a0.z = fmaf(m0.z, rv.z, a0.z); a0.w = fmaf(m0.w, rv.w, a0.w);
        a1.x = fmaf(m1.x, rv.x, a1.x); a1.y = fmaf(m1.y, rv.y, a1.y);
        a1.z = fmaf(m1.z, rv.z, a1.z); a1.w = fmaf(m1.w, rv.w, a1.w);
    }

    float4* agg4 = (float4*)agg;
    agg4[nid * 32 + lane] = a0;
    agg4[ND4 + nid * 32 + lane] = a1;
}

// ============================================================================
// Kernel 3: upd = relu([h|agg] @ W_upd^T + b); out = LN(h + upd)
// mma.sync tf32x3, K=256 in 8 chunks (0-3: h cols, 4-7: agg cols).
// ============================================================================
__global__ __launch_bounds__(256) void update_ln_mma(
    const float* __restrict__ h, const float* __restrict__ agg,
    const float* __restrict__ Wupd, const float* __restrict__ bupd,
    const float* __restrict__ lns, const float* __restrict__ lnb,
    float* __restrict__ out, int rows)
{
    extern __shared__ float sm[];
    float* Ash = sm + OF_ASH;
    float* Asl = sm + OF_ASL;
    float* Bsh = sm + OF_BSH;
    float* Bsl = sm + OF_BSL;

    const int tid = threadIdx.x;
    const int lane = tid & 31, wid = tid >> 5;
    const int g = lane >> 2, q = lane & 3;
    const int m0 = (wid >> 2) * 32, n0 = (wid & 3) * 32;
    const int warp_n = wid & 3;
    const int row0 = blockIdx.x * 64;

    const float4* h4 = (const float4*)h;
    const float4* a4 = (const float4*)agg;
    const float4* W4 = (const float4*)Wupd;    // row stride 64 float4

    float c[2][4][4];
    #pragma unroll
    for (int mt = 0; mt < 2; ++mt)
        #pragma unroll
        for (int nt = 0; nt < 4; ++nt)
            #pragma unroll
            for (int k = 0; k < 4; ++k) c[mt][nt][k] = 0.f;

    for (int ch = 0; ch < 8; ++ch) {
        const float4* src4 = (ch < 4) ? h4 : a4;
        const int scol8 = (ch & 3) * 8;
        #pragma unroll
        for (int i = tid; i < 512; i += 256) {
            const int r = i >> 3, j4 = i & 7;
            const int gr = row0 + r;
            float4 v = (gr < rows) ? src4[gr * 32 + scol8 + j4]
                                   : make_float4(0.f, 0.f, 0.f, 0.f);
            float4 hi, lo;
            split_tf32(v.x, hi.x, lo.x);
            split_tf32(v.y, hi.y, lo.y);
            split_tf32(v.z, hi.z, lo.z);
            split_tf32(v.w, hi.w, lo.w);
            *(float4*)&Ash[r * SA_STR + j4 * 4] = hi;
            *(float4*)&Asl[r * SA_STR + j4 * 4] = lo;
        }
        #pragma unroll
        for (int i = tid; i < 1024; i += 256) {
            const int r = i >> 3, j4 = i & 7;
            float4 w = W4[r * 64 + ch * 8 + j4];
            float4 hi, lo;
            split_tf32(w.x, hi.x, lo.x);
            split_tf32(w.y, hi.y, lo.y);
            split_tf32(w.z, hi.z, lo.z);
            split_tf32(w.w, hi.w, lo.w);
            *(float4*)&Bsh[r * SA_STR + j4 * 4] = hi;
            *(float4*)&Bsl[r * SA_STR + j4 * 4] = lo;
        }
        __syncthreads();

        #pragma unroll
        for (int ks = 0; ks < 4; ++ks) {
            const int kc = ks * 8;
            float ah[2][4], al[2][4], bh[4][2], bl[4][2];
            #pragma unroll
            for (int mt = 0; mt < 2; ++mt) {
                const int rb = (m0 + mt * 16 + g) * SA_STR + kc + q;
                ah[mt][0] = Ash[rb];
                ah[mt][1] = Ash[rb + 8 * SA_STR];
                ah[mt][2] = Ash[rb + 4];
                ah[mt][3] = Ash[rb + 8 * SA_STR + 4];
                al[mt][0] = Asl[rb];
                al[mt][1] = Asl[rb + 8 * SA_STR];
                al[mt][2] = Asl[rb + 4];
                al[mt][3] = Asl[rb + 8 * SA_STR + 4];
            }
            #pragma unroll
            for (int nt = 0; nt < 4; ++nt) {
                const int rb = (n0 + nt * 8 + g) * SA_STR + kc + q;
                bh[nt][0] = Bsh[rb];
                bh[nt][1] = Bsh[rb + 4];
                bl[nt][0] = Bsl[rb];
                bl[nt][1] = Bsl[rb + 4];
            }
            #pragma unroll
            for (int mt = 0; mt < 2; ++mt)
                #pragma unroll
                for (int nt = 0; nt < 4; ++nt) {
                    mma_tf32(c[mt][nt], ah[mt], bh[nt]);
                    mma_tf32(c[mt][nt], ah[mt], bl[nt]);
                    mma_tf32(c[mt][nt], al[mt], bh[nt]);
                }
        }
        __syncthreads();
    }

    // --- epilogue: v = relu(C + b) + h, LN across row (cross-warp via smem) ---
    float2* red = (float2*)sm;          // red[row(64)][warp_n(4)]

    float2 bias[4], lsc[4], lbi[4];
    #pragma unroll
    for (int nt = 0; nt < 4; ++nt) {
        const int col = n0 + nt * 8 + q * 2;
        bias[nt] = *(const float2*)&bupd[col];
        lsc[nt]  = *(const float2*)&lns[col];
        lbi[nt]  = *(const float2*)&lnb[col];
    }

    // compute v in-place in c, accumulate quad partial sums per (mt, half)
    float s1v[2][2], s2v[2][2];
    #pragma unroll
    for (int mt = 0; mt < 2; ++mt) {
        const int rlo = row0 + m0 + mt * 16 + g;
        const int rhi = rlo + 8;
        float p1lo = 0.f, p2lo = 0.f, p1hi = 0.f, p2hi = 0.f;
        #pragma unroll
        for (int nt = 0; nt < 4; ++nt) {
            const int col = n0 + nt * 8 + q * 2;
            float2 hlo = (rlo < rows) ? *(const float2*)&h[rlo * DD + col]
                                      : make_float2(0.f, 0.f);
            float2 hhi = (rhi < rows) ? *(const float2*)&h[rhi * DD + col]
                                      : make_float2(0.f, 0.f);
            float v0 = fmaxf(c[mt][nt][0] + bias[nt].x, 0.f) + hlo.x;
            float v1 = fmaxf(c[mt][nt][1] + bias[nt].y, 0.f) + hlo.y;
            float v2 = fmaxf(c[mt][nt][2] + bias[nt].x, 0.f) + hhi.x;
            float v3 = fmaxf(c[mt][nt][3] + bias[nt].y, 0.f) + hhi.y;
            c[mt][nt][0] = v0; c[mt][nt][1] = v1;
            c[mt][nt][2] = v2; c[mt][nt][3] = v3;
            p1lo += v0 + v1;  p2lo += v0*v0 + v1*v1;
            p1hi += v2 + v3;  p2hi += v2*v2 + v3*v3;
        }
        s1v[mt][0] = p1lo; s2v[mt][0] = p2lo;
        s1v[mt][1] = p1hi; s2v[mt][1] = p2hi;
    }
    // reduce within quad (lanes g*4+q, q=0..3)
    #pragma unroll
    for (int mt = 0; mt < 2; ++mt)
        #pragma unroll
        for (int hf = 0; hf < 2; ++hf) {
            float s1 = s1v[mt][hf], s2 = s2v[mt][hf];
            s1 += __shfl_xor_sync(0xffffffffu, s1, 1);
            s2 += __shfl_xor_sync(0xffffffffu, s2, 1);
            s1 += __shfl_xor_sync(0xffffffffu, s1, 2);
            s2 += __shfl_xor_sync(0xffffffffu, s2, 2);
            if (q == 0) {
                const int rl = m0 + mt * 16 + hf * 8 + g;
                red[rl * 4 + warp_n] = make_float2(s1, s2);
            }
        }
    __syncthreads();

    #pragma unroll
    for (int mt = 0; mt < 2; ++mt) {
        #pragma unroll
        for (int hf = 0; hf < 2; ++hf) {
            const int rl = m0 + mt * 16 + hf * 8 + g;
            const int gr = row0 + rl;
            float S1 = 0.f, S2 = 0.f;
            #pragma unroll
            for (int w = 0; w < 4; ++w) {
                float2 p = red[rl * 4 + w];
                S1 += p.x; S2 += p.y;
            }
            const float mu  = S1 * (1.f / 128.f);
            const float var = S2 * (1.f / 128.f) - mu * mu;
            const float rs  = rsqrtf(var + 1e-5f);
            if (gr < rows) {
                #pragma unroll
                for (int nt = 0; nt < 4; ++nt) {
                    const int col = n0 + nt * 8 + q * 2;
                    const float v0 = c[mt][nt][hf * 2 + 0];
                    const float v1 = c[mt][nt][hf * 2 + 1];
                    float2 o;
                    o.x = (v0 - mu) * rs * lsc[nt].x + lbi[nt].x;
                    o.y = (v1 - mu) * rs * lsc[nt].y + lbi[nt].y;
                    *(float2*)&out[gr * DD + col] = o;
                }
            }
        }
    }
}

// ============================================================================
// host
// ============================================================================
extern "C" void kernel_launch(void* const* d_in, const int* in_sizes, int n_in,
                              void* d_out, int out_size)
{
    const float* h    = (const float*)d_in[0];
    const float* Wmsg = (const float*)d_in[1];
    const float* rel  = (const float*)d_in[2];
    const float* Wupd = (const float*)d_in[3];
    const float* bupd = (const float*)d_in[4];
    const float* lns  = (const float*)d_in[5];
    const float* lnb  = (const float*)d_in[6];
    const int*   esrc = (const int*)d_in[7];
    const int*   etgt = (const int*)d_in[8];
    const int*   erel = (const int*)d_in[9];
    float* out = (float*)d_out;

    const int E    = in_sizes[7];
    const int rows = in_sizes[0] / DD;     // B*N
    const int N    = rows / 2;
    const int ND   = N * DD;
    const int tiles = (rows + 63) / 64;

    void *pm, *pa, *pc, *pb, *ps;
    cudaGetSymbolAddress(&pm, g_m);
    cudaGetSymbolAddress(&pa, g_agg);
    cudaGetSymbolAddress(&pc, g_cnt);
    cudaGetSymbolAddress(&pb, g_base);
    cudaGetSymbolAddress(&ps, g_sorted);
    float* d_m    = (float*)pm;
    float* d_agg  = (float*)pa;
    int*   d_cnt  = (int*)pc;
    int*   d_base = (int*)pb;
    int*   d_sort = (int*)ps;

    cudaFuncSetAttribute(msg_gemm_mma,  cudaFuncAttributeMaxDynamicSharedMemorySize, SM_BYTES);
    cudaFuncSetAttribute(update_ln_mma, cudaFuncAttributeMaxDynamicSharedMemorySize, SM_BYTES);

    // edge sort (counting sort by target)
    cudaMemsetAsync(d_cnt, 0, (size_t)N * sizeof(int), 0);
    hist_k<<<(E + 255) / 256, 256>>>(etgt, d_cnt, E);
    exscan_k<<<1, 1024>>>(d_cnt, d_base, N);
    fill_k<<<(E + 255) / 256, 256>>>(esrc, etgt, erel, d_base, d_sort, E);

    // m = h @ W_msg^T
    msg_gemm_mma<<<tiles, 256, SM_BYTES>>>(h, Wmsg, d_m, rows);

    // agg[t] = sum_{e: tgt=t} m[src_e] * rel_emb[rel_e]
    gather_csr<<<(N + 7) / 8, 256>>>(d_m, rel, d_base, d_sort, d_agg, N, ND);

    // update + residual + layernorm
    update_ln_mma<<<tiles, 256, SM_BYTES>>>(h, d_agg, Wupd, bupd, lns, lnb, out, rows);
}